// round 13
// baseline (speedup 1.0000x reference)
#include <cuda_runtime.h>
#include <cuda_fp16.h>
#include <math.h>
#include <stdint.h>

// ---------------- problem constants ----------------
#define NE 8
#define HD 1024
#define FD 4096
#define NT 8192
#define MAXT 72                                  // max live m-tiles

// ---------------- GEMM tile config (fp16, m16n8k16) ----------------
#define BM 128
#define BN 256
#define BK 64                                    // 64 halves = 128B row
#define STAGES 4
#define A_STAGE_BYTES (BM * BK * 2)              // 16384
#define B_STAGE_BYTES (BN * BK * 2)              // 32768
#define STAGE_BYTES   (A_STAGE_BYTES + B_STAGE_BYTES)   // 49152
#define SMEM_BYTES    (STAGES * STAGE_BYTES)            // 196608

// prep kernel block ranges
#define PREP_W1_BLKS 4096
#define PREP_X_BLKS  1024

// w2 conversion slicing inside the persistent kernel
#define NW2 256                                  // w2 cvt slices
#define W2_N8 (NE * HD * FD / 8)                 // 4194304 uint4 units
#define W2_PER (W2_N8 / NW2)                     // 16384 per slice

#define NSM 152                                  // GB300 SM count

// ---------------- device scratch ----------------
__device__ __align__(16) __half g_w1h[(size_t)NE * FD * HD];
__device__ __align__(16) __half g_w2h[(size_t)NE * HD * FD];
__device__ __align__(16) __half g_xh[(size_t)NT * HD];
__device__ __align__(16) __half g_hbuf[(size_t)NT * FD];   // gelu(fc1), sorted order
__device__ int g_perm[NT];
__device__ int g_off[NE + 1];
__device__ int g_tile_e[MAXT], g_tile_m[MAXT], g_ntiles;
// work queue state (re-initialized by k_prep every call -> graph-replay safe)
__device__ int g_qhead;
__device__ int g_total_p1, g_total;
__device__ int g_done_cnt[MAXT];                 // fc1 n-blocks completed per mtile
__device__ int g_w2done;                         // completed w2 slices

// ---------------- helpers ----------------
__device__ __forceinline__ uint32_t smem_u32(const void* p) {
    uint32_t a;
    asm("{ .reg .u64 t; cvta.to.shared.u64 t, %1; cvt.u32.u64 %0, t; }" : "=r"(a) : "l"(p));
    return a;
}
__device__ __forceinline__ void cp16(uint32_t dst, const void* src) {
    asm volatile("cp.async.cg.shared.global [%0], [%1], 16;" :: "r"(dst), "l"(src));
}
__device__ __forceinline__ void cp_commit() {
    asm volatile("cp.async.commit_group;" ::: "memory");
}
template <int N>
__device__ __forceinline__ void cp_wait() {
    asm volatile("cp.async.wait_group %0;" :: "n"(N) : "memory");
}
__device__ __forceinline__ void ldsm_x4(uint32_t* r, uint32_t addr) {
    asm volatile("ldmatrix.sync.aligned.m8n8.x4.shared.b16 {%0,%1,%2,%3}, [%4];"
                 : "=r"(r[0]), "=r"(r[1]), "=r"(r[2]), "=r"(r[3]) : "r"(addr));
}
__device__ __forceinline__ void mma_f16(float* c, const uint32_t* a, uint32_t b0, uint32_t b1) {
    asm volatile(
        "mma.sync.aligned.m16n8k16.row.col.f32.f16.f16.f32 "
        "{%0,%1,%2,%3}, {%4,%5,%6,%7}, {%8,%9}, {%0,%1,%2,%3};"
        : "+f"(c[0]), "+f"(c[1]), "+f"(c[2]), "+f"(c[3])
        : "r"(a[0]), "r"(a[1]), "r"(a[2]), "r"(a[3]), "r"(b0), "r"(b1));
}
__device__ __forceinline__ float gelu_exact(float v) {
    return 0.5f * v * (1.0f + erff(v * 0.7071067811865476f));
}
__device__ __forceinline__ void cvt8(const float4* __restrict__ src, uint4* __restrict__ dst, int i) {
    float4 v0 = src[i * 2];
    float4 v1 = src[i * 2 + 1];
    __half2 h0 = __floats2half2_rn(v0.x, v0.y);
    __half2 h1 = __floats2half2_rn(v0.z, v0.w);
    __half2 h2 = __floats2half2_rn(v1.x, v1.y);
    __half2 h3 = __floats2half2_rn(v1.z, v1.w);
    uint4 o;
    o.x = *(uint32_t*)&h0; o.y = *(uint32_t*)&h1;
    o.z = *(uint32_t*)&h2; o.w = *(uint32_t*)&h3;
    dst[i] = o;
}

// ---------------- fused prep: routing + queue init (block 0) + w1 cvt + x cvt ----------------
__global__ void k_prep(const int* __restrict__ ex,
                       const float4* __restrict__ w1f,
                       const float4* __restrict__ xf)
{
    const int b   = blockIdx.x;
    const int tid = threadIdx.x;

    if (b == 0) {
        __shared__ int s_cnt[NE], s_off[NE + 1], s_cur[NE];
        if (tid < NE) { s_cnt[tid] = 0; s_cur[tid] = 0; }
        if (tid < MAXT) g_done_cnt[tid] = 0;
        if (tid == 0) { g_qhead = 0; g_w2done = 0; }
        __syncthreads();
        for (int i = tid; i < NT; i += blockDim.x)
            atomicAdd(&s_cnt[ex[i]], 1);
        __syncthreads();
        if (tid == 0) {
            int s = 0, nt = 0;
            for (int e = 0; e < NE; e++) {
                s_off[e] = s;
                g_off[e] = s;
                for (int m0 = 0; m0 < s_cnt[e]; m0 += BM) {
                    g_tile_e[nt] = e; g_tile_m[nt] = m0; nt++;
                }
                s += s_cnt[e];
            }
            s_off[NE] = s;
            g_off[NE] = s;
            g_ntiles   = nt;
            g_total_p1 = nt * 16 + NW2;
            g_total    = nt * 16 + NW2 + nt * 4;
        }
        __syncthreads();
        for (int i = tid; i < NT; i += blockDim.x) {
            int e = ex[i];
            int r = atomicAdd(&s_cur[e], 1);
            g_perm[s_off[e] + r] = i;
        }
        return;
    }

    if (b <= PREP_W1_BLKS) {
        const int cid = b - 1;
        const int n8  = NE * FD * HD / 8;
        const int stride = PREP_W1_BLKS * 256;
        uint4* dst = (uint4*)g_w1h;
        for (int i = cid * 256 + tid; i < n8; i += stride)
            cvt8(w1f, dst, i);
        return;
    }

    {
        const int cid = b - 1 - PREP_W1_BLKS;
        const int n8  = NT * HD / 8;
        const int stride = PREP_X_BLKS * 256;
        uint4* dst = (uint4*)g_xh;
        for (int i = cid * 256 + tid; i < n8; i += stride)
            cvt8(xf, dst, i);
    }
}

// ---------------- GEMM tile body (shared by fc1 / fc2) ----------------
template <int KTOT, bool FC1>
__device__ __forceinline__ void gemm_tile(
    char* smem, int tid,
    int e, int m0, int seg0, int mlen, int n0,
    const __half* __restrict__ Agm,
    const __half* __restrict__ Wh,
    const float*  __restrict__ gate,
    const int*    __restrict__ new_index,
    float*        __restrict__ outp)
{
    const int wid = tid >> 5;
    const int lid = tid & 31;
    const int wm  = wid & 1;
    const int wn  = wid >> 1;

    const uint32_t smem_b = smem_u32(smem);

    const int grow = tid >> 1;
    const int c4b  = (tid & 1) * 4;

    int arow_t = m0 + grow;
    if (arow_t >= mlen) arow_t = mlen - 1;
    const int arow = FC1 ? g_perm[seg0 + arow_t] : (seg0 + arow_t);
    const __half* aSrc = Agm + (size_t)arow * KTOT + c4b * 8;

    const __half* wbase = Wh + (size_t)e * ((size_t)(FC1 ? FD : HD) * KTOT);
    const __half* bSrc0 = wbase + (size_t)(n0 + grow)       * KTOT + c4b * 8;
    const __half* bSrc1 = wbase + (size_t)(n0 + grow + 128) * KTOT + c4b * 8;

    uint32_t offA[4], offB1[4];
#pragma unroll
    for (int j = 0; j < 4; j++) {
        offA[j]  = (uint32_t)grow * 128u + (uint32_t)(((c4b + j) ^ (grow & 7)) << 4);
        offB1[j] = (uint32_t)(grow + 128) * 128u +
                   (uint32_t)(((c4b + j) ^ ((grow + 128) & 7)) << 4);
    }

    const int lr  = lid & 7;
    const int lmi = lid >> 3;
    const int rowA0 = wm * 64 + ((lmi & 1) << 3) + lr;
    const int rowB0 = wn * 64 + ((lmi & 1) << 3) + lr;
    const int kHalf = lmi >> 1;
    const int s7A = rowA0 & 7;
    const int s7B = rowB0 & 7;

    float acc[4][8][4];
#pragma unroll
    for (int i = 0; i < 4; i++)
#pragma unroll
        for (int j = 0; j < 8; j++)
#pragma unroll
            for (int q = 0; q < 4; q++) acc[i][j][q] = 0.f;

    const int T = KTOT / BK;

    auto fill = [&](int s, int kt) {
        const uint32_t sa = smem_b + (uint32_t)s * STAGE_BYTES;
        const uint32_t sb = sa + A_STAGE_BYTES;
        const __half* a  = aSrc  + kt * BK;
        const __half* b0 = bSrc0 + kt * BK;
        const __half* b1 = bSrc1 + kt * BK;
#pragma unroll
        for (int j = 0; j < 4; j++) cp16(sa + offA[j],  a  + j * 8);
#pragma unroll
        for (int j = 0; j < 4; j++) cp16(sb + offA[j],  b0 + j * 8);
#pragma unroll
        for (int j = 0; j < 4; j++) cp16(sb + offB1[j], b1 + j * 8);
    };

#pragma unroll
    for (int s = 0; s < STAGES - 1; s++) { fill(s, s); cp_commit(); }

    for (int kt = 0; kt < T; kt++) {
        cp_wait<STAGES - 2>();
        __syncthreads();

        if (kt + STAGES - 1 < T) fill((kt + STAGES - 1) % STAGES, kt + STAGES - 1);
        cp_commit();

        const int s = kt % STAGES;
        const uint32_t aBase = smem_b + (uint32_t)s * STAGE_BYTES + (uint32_t)rowA0 * 128u;
        const uint32_t bBase = smem_b + (uint32_t)s * STAGE_BYTES + A_STAGE_BYTES +
                               (uint32_t)rowB0 * 128u;

#pragma unroll
        for (int kk = 0; kk < 4; kk++) {
            const uint32_t swA = (uint32_t)(((2 * kk + kHalf) ^ s7A) << 4);
            const uint32_t swB = (uint32_t)(((2 * kk + kHalf) ^ s7B) << 4);

            uint32_t af[4][4];
#pragma unroll
            for (int fm = 0; fm < 4; fm++)
                ldsm_x4(af[fm], aBase + (uint32_t)fm * 2048u + swA);

            uint32_t bf[4][4];
#pragma unroll
            for (int fn = 0; fn < 4; fn++)
                ldsm_x4(bf[fn], bBase + (uint32_t)fn * 2048u + swB);

#pragma unroll
            for (int fm = 0; fm < 4; fm++)
#pragma unroll
                for (int fn = 0; fn < 4; fn++) {
                    mma_f16(acc[fm][2 * fn + 0], af[fm], bf[fn][0], bf[fn][2]);
                    mma_f16(acc[fm][2 * fn + 1], af[fm], bf[fn][1], bf[fn][3]);
                }
        }
    }

    // ---- epilogue ----
    const int g = lid >> 2;
    const int q = lid & 3;

    if (FC1) {
#pragma unroll
        for (int fm = 0; fm < 4; fm++) {
#pragma unroll
            for (int h = 0; h < 2; h++) {
                const int row = m0 + wm * 64 + fm * 16 + h * 8 + g;
                if (row < mlen) {
                    __half* dst = g_hbuf + (size_t)(seg0 + row) * FD + n0 + wn * 64 + q * 2;
#pragma unroll
                    for (int fn = 0; fn < 8; fn++) {
                        __half2 v = __floats2half2_rn(gelu_exact(acc[fm][fn][h * 2 + 0]),
                                                      gelu_exact(acc[fm][fn][h * 2 + 1]));
                        *(__half2*)(dst + fn * 8) = v;
                    }
                }
            }
        }
    } else {
#pragma unroll
        for (int fm = 0; fm < 4; fm++) {
#pragma unroll
            for (int h = 0; h < 2; h++) {
                const int row = m0 + wm * 64 + fm * 16 + h * 8 + g;
                if (row < mlen) {
                    const int orig = g_perm[seg0 + row];
                    const float gg = gate[orig];
                    const int   dest = new_index[orig] >> 1;
                    float* orow = outp + (size_t)dest * HD + n0 + wn * 64 + q * 2;
#pragma unroll
                    for (int fn = 0; fn < 8; fn++) {
                        atomicAdd(orow + fn * 8 + 0, acc[fm][fn][h * 2 + 0] * gg);
                        atomicAdd(orow + fn * 8 + 1, acc[fm][fn][h * 2 + 1] * gg);
                    }
                }
            }
        }
    }
}

// ---------------- persistent fused MoE kernel ----------------
// Work queue (monotonic): items [0, total_p1): fc1 tiles (mtile-major) with 256
// w2-cvt slices interleaved at positions it%5==2 (first 256 such). Items
// [total_p1, total): fc2 tiles gated on per-mtile fc1 completion + w2 done.

__global__ __launch_bounds__(256, 1)
void k_moe(const float* __restrict__ w2f,
           const float* __restrict__ gate,
           const int*   __restrict__ new_index,
           float*       __restrict__ outp)
{
    extern __shared__ __align__(128) char smem[];
    __shared__ int s_it;
    const int tid = threadIdx.x;

    for (;;) {
        if (tid == 0) s_it = atomicAdd(&g_qhead, 1);
        __syncthreads();
        const int it = s_it;
        if (it >= g_total) return;

        if (it < g_total_p1) {
            const bool isw2 = ((it % 5) == 2) && ((it / 5) < NW2);
            if (isw2) {
                // ---- w2 cvt slice ----
                const int w = it / 5;
                const float4* src = (const float4*)w2f;
                uint4*        dst = (uint4*)g_w2h;
                const int i0 = w * W2_PER;
                for (int i = i0 + tid; i < i0 + W2_PER; i += 256)
                    cvt8(src, dst, i);
                __threadfence();
                __syncthreads();
                if (tid == 0) atomicAdd(&g_w2done, 1);
            } else {
                // ---- fc1 tile ----
                const int nb = (it >= 2) ? min(NW2, (it + 2) / 5) : 0;
                const int f  = it - nb;
                const int mt = f >> 4;
                const int nblk = f & 15;
                const int e    = g_tile_e[mt];
                const int m0   = g_tile_m[mt];
                const int seg0 = g_off[e];
                const int mlen = g_off[e + 1] - seg0;
                gemm_tile<HD, true>(smem, tid, e, m0, seg0, mlen, nblk * BN,
                                    g_xh, g_w1h, gate, new_index, outp);
                __threadfence();
                __syncthreads();
                if (tid == 0) atomicAdd(&g_done_cnt[mt], 1);
            }
        } else {
            // ---- fc2 tile (dependency-gated) ----
            const int f2 = it - g_total_p1;
            const int mt = f2 >> 2;
            const int nblk = f2 & 3;
            if (tid == 0) {
                volatile int* c = &g_done_cnt[mt];
                volatile int* w = &g_w2done;
                while (*c < 16 || *w < NW2) { }
            }
            __syncthreads();
            __threadfence();
            const int e    = g_tile_e[mt];
            const int m0   = g_tile_m[mt];
            const int seg0 = g_off[e];
            const int mlen = g_off[e + 1] - seg0;
            gemm_tile<FD, false>(smem, tid, e, m0, seg0, mlen, nblk * BN,
                                 g_hbuf, g_w2h, gate, new_index, outp);
        }
        __syncthreads();   // protect s_it and smem reuse across items
    }
}

// ---------------- launch ----------------
extern "C" void kernel_launch(void* const* d_in, const int* in_sizes, int n_in,
                              void* d_out, int out_size) {
    const float* x         = (const float*)d_in[0];
    const float* gate      = (const float*)d_in[1];
    const int*   experts   = (const int*)  d_in[2];
    const int*   new_index = (const int*)  d_in[3];
    const float* w1        = (const float*)d_in[4];
    const float* w2        = (const float*)d_in[5];
    float*       out       = (float*)d_out;

    cudaFuncSetAttribute(k_moe, cudaFuncAttributeMaxDynamicSharedMemorySize, SMEM_BYTES);

    cudaMemsetAsync(d_out, 0, (size_t)out_size * sizeof(float), 0);

    // fused prep: block 0 routing + queue init; blocks 1..4096 w1 cvt; then x cvt
    k_prep<<<1 + PREP_W1_BLKS + PREP_X_BLKS, 256>>>(
        experts, (const float4*)w1, (const float4*)x);

    // persistent fused fc1 + w2cvt + fc2
    k_moe<<<NSM, 256, SMEM_BYTES>>>(w2, gate, new_index, out);
}

// round 14
// speedup vs baseline: 1.1815x; 1.1815x over previous
#include <cuda_runtime.h>
#include <cuda_fp16.h>
#include <math.h>
#include <stdint.h>

// ---------------- problem constants ----------------
#define NE 8
#define HD 1024
#define FD 4096
#define NT 8192
#define MAXT 72                                  // max live m-tiles

// ---------------- GEMM tile config (fp16, m16n8k16), 512 threads ----------------
#define BM 128
#define BN 256
#define BK 64                                    // 64 halves = 128B row
#define STAGES 4
#define A_STAGE_BYTES (BM * BK * 2)              // 16384
#define B_STAGE_BYTES (BN * BK * 2)              // 32768
#define STAGE_BYTES   (A_STAGE_BYTES + B_STAGE_BYTES)   // 49152
#define SMEM_BYTES    (STAGES * STAGE_BYTES)            // 196608

// prep kernel block ranges
#define PREP_W1_BLKS 4096
#define PREP_X_BLKS  1024

// ---------------- device scratch ----------------
__device__ __align__(16) __half g_w1h[(size_t)NE * FD * HD];
__device__ __align__(16) __half g_w2h[(size_t)NE * HD * FD];
__device__ __align__(16) __half g_xh[(size_t)NT * HD];
__device__ __align__(16) __half g_hbuf[(size_t)NT * FD];   // gelu(fc1), sorted order
__device__ int g_perm[NT];
__device__ int g_off[NE + 1];
__device__ int g_tile_e[MAXT], g_tile_m[MAXT], g_ntiles;

// ---------------- helpers ----------------
__device__ __forceinline__ uint32_t smem_u32(const void* p) {
    uint32_t a;
    asm("{ .reg .u64 t; cvta.to.shared.u64 t, %1; cvt.u32.u64 %0, t; }" : "=r"(a) : "l"(p));
    return a;
}
__device__ __forceinline__ void cp16(uint32_t dst, const void* src) {
    asm volatile("cp.async.cg.shared.global [%0], [%1], 16;" :: "r"(dst), "l"(src));
}
__device__ __forceinline__ void cp_commit() {
    asm volatile("cp.async.commit_group;" ::: "memory");
}
template <int N>
__device__ __forceinline__ void cp_wait() {
    asm volatile("cp.async.wait_group %0;" :: "n"(N) : "memory");
}
__device__ __forceinline__ void ldsm_x4(uint32_t* r, uint32_t addr) {
    asm volatile("ldmatrix.sync.aligned.m8n8.x4.shared.b16 {%0,%1,%2,%3}, [%4];"
                 : "=r"(r[0]), "=r"(r[1]), "=r"(r[2]), "=r"(r[3]) : "r"(addr));
}
__device__ __forceinline__ void mma_f16(float* c, const uint32_t* a, uint32_t b0, uint32_t b1) {
    asm volatile(
        "mma.sync.aligned.m16n8k16.row.col.f32.f16.f16.f32 "
        "{%0,%1,%2,%3}, {%4,%5,%6,%7}, {%8,%9}, {%0,%1,%2,%3};"
        : "+f"(c[0]), "+f"(c[1]), "+f"(c[2]), "+f"(c[3])
        : "r"(a[0]), "r"(a[1]), "r"(a[2]), "r"(a[3]), "r"(b0), "r"(b1));
}
__device__ __forceinline__ float gelu_exact(float v) {
    return 0.5f * v * (1.0f + erff(v * 0.7071067811865476f));
}
__device__ __forceinline__ void cvt8(const float4* __restrict__ src, uint4* __restrict__ dst, int i) {
    float4 v0 = src[i * 2];
    float4 v1 = src[i * 2 + 1];
    __half2 h0 = __floats2half2_rn(v0.x, v0.y);
    __half2 h1 = __floats2half2_rn(v0.z, v0.w);
    __half2 h2 = __floats2half2_rn(v1.x, v1.y);
    __half2 h3 = __floats2half2_rn(v1.z, v1.w);
    uint4 o;
    o.x = *(uint32_t*)&h0; o.y = *(uint32_t*)&h1;
    o.z = *(uint32_t*)&h2; o.w = *(uint32_t*)&h3;
    dst[i] = o;
}

// ---------------- fused prep: routing (block 0) + w1 cvt + x cvt ----------------
__global__ void k_prep(const int* __restrict__ ex,
                       const float4* __restrict__ w1f,
                       const float4* __restrict__ xf)
{
    const int b   = blockIdx.x;
    const int tid = threadIdx.x;

    if (b == 0) {
        __shared__ int s_cnt[NE], s_off[NE + 1], s_cur[NE];
        if (tid < NE) { s_cnt[tid] = 0; s_cur[tid] = 0; }
        __syncthreads();
        for (int i = tid; i < NT; i += blockDim.x)
            atomicAdd(&s_cnt[ex[i]], 1);
        __syncthreads();
        if (tid == 0) {
            int s = 0, nt = 0;
            for (int e = 0; e < NE; e++) {
                s_off[e] = s;
                g_off[e] = s;
                for (int m0 = 0; m0 < s_cnt[e]; m0 += BM) {
                    g_tile_e[nt] = e; g_tile_m[nt] = m0; nt++;
                }
                s += s_cnt[e];
            }
            s_off[NE] = s;
            g_off[NE] = s;
            g_ntiles  = nt;
        }
        __syncthreads();
        for (int i = tid; i < NT; i += blockDim.x) {
            int e = ex[i];
            int r = atomicAdd(&s_cur[e], 1);
            g_perm[s_off[e] + r] = i;
        }
        return;
    }

    if (b <= PREP_W1_BLKS) {
        const int cid = b - 1;
        const int n8  = NE * FD * HD / 8;
        const int stride = PREP_W1_BLKS * 256;
        uint4* dst = (uint4*)g_w1h;
        for (int i = cid * 256 + tid; i < n8; i += stride)
            cvt8(w1f, dst, i);
        return;
    }

    {
        const int cid = b - 1 - PREP_W1_BLKS;
        const int n8  = NT * HD / 8;
        const int stride = PREP_X_BLKS * 256;
        uint4* dst = (uint4*)g_xh;
        for (int i = cid * 256 + tid; i < n8; i += stride)
            cvt8(xf, dst, i);
    }
}

// ---------------- fp16 mma.sync grouped GEMM (512 threads, 16 warps) ----------------
// warp grid: 2 m-halves (64 rows) x 8 n-slots (32 cols). acc = 64 regs/thread.
// blockIdx.y < g_ntiles: GEMM m-tile. FC1 blockIdx.y >= MAXT: w2 cvt slices.

template <int KTOT, bool FC1>
__global__ __launch_bounds__(512, 1)
void k_gemm(const __half* __restrict__ Agm,
            const __half* __restrict__ Wh,
            const float*  __restrict__ gate,
            const int*    __restrict__ new_index,
            float*        __restrict__ outp,
            const float*  __restrict__ w2f)
{
    extern __shared__ __align__(128) char smem[];

    const int tid = threadIdx.x;

    if (FC1 && blockIdx.y >= MAXT) {
        // ---- w2 fp32 -> fp16 conversion slice (scheduled last) ----
        const int  cid    = (blockIdx.y - MAXT) * gridDim.x + blockIdx.x;   // 0..255
        const int  n8     = NE * HD * FD / 8;
        const int  stride = 256 * 512;
        const float4* src = (const float4*)w2f;
        uint4*        dst = (uint4*)g_w2h;
        for (int i = cid * 512 + tid; i < n8; i += stride)
            cvt8(src, dst, i);
        return;
    }

    if ((int)blockIdx.y >= g_ntiles) return;
    const int e    = g_tile_e[blockIdx.y];
    const int m0   = g_tile_m[blockIdx.y];
    const int seg0 = g_off[e];
    const int mlen = g_off[e + 1] - seg0;
    const int n0   = blockIdx.x * BN;

    const int wid = tid >> 5;
    const int lid = tid & 31;
    const int wm  = wid & 1;       // m half (64 rows)
    const int wn  = wid >> 1;      // n slot (32 cols), 0..7

    const uint32_t smem_b = smem_u32(smem);

    // ---- gmem load mapping ----
    // A: thread t -> row t>>2 (0..127), 2 chunks of 16B at chunk base (t&3)*2
    // B: thread t -> row t>>1 (0..255), 4 chunks of 16B at chunk base (t&1)*4
    const int arowL = tid >> 2;
    const int acb   = (tid & 3) * 2;
    const int browL = tid >> 1;
    const int bcb   = (tid & 1) * 4;

    int arow_t = m0 + arowL;
    if (arow_t >= mlen) arow_t = mlen - 1;          // clamp; masked in epilogue
    const int arow = FC1 ? g_perm[seg0 + arow_t] : (seg0 + arow_t);
    const __half* aSrc = Agm + (size_t)arow * KTOT + acb * 8;

    const __half* wbase = Wh + (size_t)e * ((size_t)(FC1 ? FD : HD) * KTOT);
    const __half* bSrc  = wbase + (size_t)(n0 + browL) * KTOT + bcb * 8;

    uint32_t offA[2], offB[4];
#pragma unroll
    for (int j = 0; j < 2; j++)
        offA[j] = (uint32_t)arowL * 128u + (uint32_t)(((acb + j) ^ (arowL & 7)) << 4);
#pragma unroll
    for (int j = 0; j < 4; j++)
        offB[j] = (uint32_t)browL * 128u + (uint32_t)(((bcb + j) ^ (browL & 7)) << 4);

    // ---- ldmatrix per-lane address components ----
    const int lr  = lid & 7;
    const int lmi = lid >> 3;
    const int rowA0 = wm * 64 + ((lmi & 1) << 3) + lr;
    const int rowB0 = wn * 32 + ((lmi & 1) << 3) + lr;
    const int kHalf = lmi >> 1;
    const int s7A = rowA0 & 7;
    const int s7B = rowB0 & 7;

    float acc[4][4][4];
#pragma unroll
    for (int i = 0; i < 4; i++)
#pragma unroll
        for (int j = 0; j < 4; j++)
#pragma unroll
            for (int q = 0; q < 4; q++) acc[i][j][q] = 0.f;

    const int T = KTOT / BK;

    auto fill = [&](int s, int kt) {
        const uint32_t sa = smem_b + (uint32_t)s * STAGE_BYTES;
        const uint32_t sb = sa + A_STAGE_BYTES;
        const __half* a = aSrc + kt * BK;
        const __half* b = bSrc + kt * BK;
#pragma unroll
        for (int j = 0; j < 2; j++) cp16(sa + offA[j], a + j * 8);
#pragma unroll
        for (int j = 0; j < 4; j++) cp16(sb + offB[j], b + j * 8);
    };

#pragma unroll
    for (int s = 0; s < STAGES - 1; s++) { fill(s, s); cp_commit(); }

    for (int kt = 0; kt < T; kt++) {
        cp_wait<STAGES - 2>();
        __syncthreads();       // single barrier per iteration

        if (kt + STAGES - 1 < T) fill((kt + STAGES - 1) % STAGES, kt + STAGES - 1);
        cp_commit();

        const int s = kt % STAGES;
        const uint32_t aBase = smem_b + (uint32_t)s * STAGE_BYTES + (uint32_t)rowA0 * 128u;
        const uint32_t bBase = smem_b + (uint32_t)s * STAGE_BYTES + A_STAGE_BYTES +
                               (uint32_t)rowB0 * 128u;

#pragma unroll
        for (int kk = 0; kk < 4; kk++) {
            const uint32_t swA = (uint32_t)(((2 * kk + kHalf) ^ s7A) << 4);
            const uint32_t swB = (uint32_t)(((2 * kk + kHalf) ^ s7B) << 4);

            uint32_t af[4][4];
#pragma unroll
            for (int fm = 0; fm < 4; fm++)
                ldsm_x4(af[fm], aBase + (uint32_t)fm * 2048u + swA);

            uint32_t bf[2][4];
#pragma unroll
            for (int fn = 0; fn < 2; fn++)
                ldsm_x4(bf[fn], bBase + (uint32_t)fn * 2048u + swB);

#pragma unroll
            for (int fm = 0; fm < 4; fm++)
#pragma unroll
                for (int fn = 0; fn < 2; fn++) {
                    mma_f16(acc[fm][2 * fn + 0], af[fm], bf[fn][0], bf[fn][2]);
                    mma_f16(acc[fm][2 * fn + 1], af[fm], bf[fn][1], bf[fn][3]);
                }
        }
    }

    // ---- epilogue ----
    const int g = lid >> 2;
    const int q = lid & 3;

    if (FC1) {
#pragma unroll
        for (int fm = 0; fm < 4; fm++) {
#pragma unroll
            for (int h = 0; h < 2; h++) {
                const int row = m0 + wm * 64 + fm * 16 + h * 8 + g;
                if (row < mlen) {
                    __half* dst = g_hbuf + (size_t)(seg0 + row) * FD + n0 + wn * 32 + q * 2;
#pragma unroll
                    for (int fn = 0; fn < 4; fn++) {
                        __half2 v = __floats2half2_rn(gelu_exact(acc[fm][fn][h * 2 + 0]),
                                                      gelu_exact(acc[fm][fn][h * 2 + 1]));
                        *(__half2*)(dst + fn * 8) = v;
                    }
                }
            }
        }
    } else {
#pragma unroll
        for (int fm = 0; fm < 4; fm++) {
#pragma unroll
            for (int h = 0; h < 2; h++) {
                const int row = m0 + wm * 64 + fm * 16 + h * 8 + g;
                if (row < mlen) {
                    const int orig = g_perm[seg0 + row];
                    const float gg = gate[orig];
                    const int   dest = new_index[orig] >> 1;
                    float* orow = outp + (size_t)dest * HD + n0 + wn * 32 + q * 2;
#pragma unroll
                    for (int fn = 0; fn < 4; fn++) {
                        atomicAdd(orow + fn * 8 + 0, acc[fm][fn][h * 2 + 0] * gg);
                        atomicAdd(orow + fn * 8 + 1, acc[fm][fn][h * 2 + 1] * gg);
                    }
                }
            }
        }
    }
}

// ---------------- launch ----------------
extern "C" void kernel_launch(void* const* d_in, const int* in_sizes, int n_in,
                              void* d_out, int out_size) {
    const float* x         = (const float*)d_in[0];
    const float* gate      = (const float*)d_in[1];
    const int*   experts   = (const int*)  d_in[2];
    const int*   new_index = (const int*)  d_in[3];
    const float* w1        = (const float*)d_in[4];
    const float* w2        = (const float*)d_in[5];
    float*       out       = (float*)d_out;

    cudaFuncSetAttribute(k_gemm<HD, true>,  cudaFuncAttributeMaxDynamicSharedMemorySize, SMEM_BYTES);
    cudaFuncSetAttribute(k_gemm<FD, false>, cudaFuncAttributeMaxDynamicSharedMemorySize, SMEM_BYTES);

    cudaMemsetAsync(d_out, 0, (size_t)out_size * sizeof(float), 0);

    __half* w2h; __half* xh; __half* w1h; __half* hbuf;
    cudaGetSymbolAddress((void**)&w1h, g_w1h);
    cudaGetSymbolAddress((void**)&w2h, g_w2h);
    cudaGetSymbolAddress((void**)&xh,  g_xh);
    cudaGetSymbolAddress((void**)&hbuf, g_hbuf);

    // fused prep: block 0 routing; blocks 1..4096 w1 cvt; 4097..5120 x cvt
    k_prep<<<1 + PREP_W1_BLKS + PREP_X_BLKS, 256>>>(
        experts, (const float4*)w1, (const float4*)x);

    // fc1: gelu(x @ w1^T) -> g_hbuf; + 16 trailing y-blocks convert w2 -> g_w2h
    k_gemm<HD, true><<<dim3(FD / BN, MAXT + 16), 512, SMEM_BYTES>>>(
        xh, w1h, gate, new_index, out, w2);
    // fc2: (hbuf @ w2^T) * gate -> atomicAdd topk-scatter
    k_gemm<FD, false><<<dim3(HD / BN, MAXT), 512, SMEM_BYTES>>>(
        hbuf, w2h, gate, new_index, out, nullptr);
}

// round 15
// speedup vs baseline: 1.3715x; 1.1608x over previous
#include <cuda_runtime.h>
#include <cuda.h>
#include <cuda_fp16.h>
#include <math.h>
#include <stdint.h>
#include <string.h>

// ---------------- problem constants ----------------
#define NE 8
#define HD 1024
#define FD 4096
#define NT 8192
#define MAXT 72                                  // max live m-tiles

// ---------------- GEMM tile config (fp16, m16n8k16), 512 threads ----------------
#define BM 128
#define BN 256
#define BK 64                                    // 64 halves = 128B row
#define STAGES 4
#define A_STAGE_BYTES (BM * BK * 2)              // 16384
#define B_STAGE_BYTES (BN * BK * 2)              // 32768
#define STAGE_BYTES   (A_STAGE_BYTES + B_STAGE_BYTES)   // 49152
#define MBAR_OFF      (STAGES * STAGE_BYTES)            // 196608
#define SMEM_BYTES    (MBAR_OFF + 64)

// prep kernel block ranges
#define PREP_W1_BLKS 4096
#define PREP_X_BLKS  1024

// ---------------- device scratch ----------------
__device__ __align__(128) __half g_w1h[(size_t)NE * FD * HD];
__device__ __align__(128) __half g_w2h[(size_t)NE * HD * FD];
__device__ __align__(128) __half g_xh[(size_t)NT * HD];
__device__ __align__(128) __half g_hbuf[(size_t)NT * FD];  // gelu(fc1), sorted order
__device__ __align__(128) unsigned char g_tmaps[3 * 128];  // 0: w1, 1: w2, 2: hbuf
__device__ int g_perm[NT];
__device__ int g_off[NE + 1];
__device__ int g_tile_e[MAXT], g_tile_m[MAXT], g_ntiles;

// ---------------- helpers ----------------
__device__ __forceinline__ uint32_t smem_u32(const void* p) {
    uint32_t a;
    asm("{ .reg .u64 t; cvta.to.shared.u64 t, %1; cvt.u32.u64 %0, t; }" : "=r"(a) : "l"(p));
    return a;
}
__device__ __forceinline__ void cp16(uint32_t dst, const void* src) {
    asm volatile("cp.async.cg.shared.global [%0], [%1], 16;" :: "r"(dst), "l"(src));
}
__device__ __forceinline__ void cp_commit() {
    asm volatile("cp.async.commit_group;" ::: "memory");
}
template <int N>
__device__ __forceinline__ void cp_wait() {
    asm volatile("cp.async.wait_group %0;" :: "n"(N) : "memory");
}
__device__ __forceinline__ void mbar_init(uint32_t mbar, uint32_t cnt) {
    asm volatile("mbarrier.init.shared.b64 [%0], %1;" :: "r"(mbar), "r"(cnt) : "memory");
}
__device__ __forceinline__ void mbar_expect_tx(uint32_t mbar, uint32_t bytes) {
    asm volatile("mbarrier.arrive.expect_tx.shared.b64 _, [%0], %1;"
                 :: "r"(mbar), "r"(bytes) : "memory");
}
__device__ __forceinline__ void mbar_wait(uint32_t mbar, uint32_t phase) {
    asm volatile(
        "{\n\t.reg .pred P;\n\t"
        "W_%=:\n\t"
        "mbarrier.try_wait.parity.shared.b64 P, [%0], %1;\n\t"
        "@P bra.uni D_%=;\n\t"
        "bra.uni W_%=;\n\t"
        "D_%=:\n\t}"
        :: "r"(mbar), "r"(phase) : "memory");
}
__device__ __forceinline__ void tma_2d(uint32_t smem_dst, const void* tmap,
                                       int x, int y, uint32_t mbar) {
    asm volatile(
        "cp.async.bulk.tensor.2d.shared::cta.global.tile.mbarrier::complete_tx::bytes "
        "[%0], [%1, {%2, %3}], [%4];"
        :: "r"(smem_dst), "l"(tmap), "r"(x), "r"(y), "r"(mbar) : "memory");
}
__device__ __forceinline__ void ldsm_x4(uint32_t* r, uint32_t addr) {
    asm volatile("ldmatrix.sync.aligned.m8n8.x4.shared.b16 {%0,%1,%2,%3}, [%4];"
                 : "=r"(r[0]), "=r"(r[1]), "=r"(r[2]), "=r"(r[3]) : "r"(addr));
}
__device__ __forceinline__ void mma_f16(float* c, const uint32_t* a, uint32_t b0, uint32_t b1) {
    asm volatile(
        "mma.sync.aligned.m16n8k16.row.col.f32.f16.f16.f32 "
        "{%0,%1,%2,%3}, {%4,%5,%6,%7}, {%8,%9}, {%0,%1,%2,%3};"
        : "+f"(c[0]), "+f"(c[1]), "+f"(c[2]), "+f"(c[3])
        : "r"(a[0]), "r"(a[1]), "r"(a[2]), "r"(a[3]), "r"(b0), "r"(b1));
}
__device__ __forceinline__ float gelu_exact(float v) {
    return 0.5f * v * (1.0f + erff(v * 0.7071067811865476f));
}
__device__ __forceinline__ void cvt8(const float4* __restrict__ src, uint4* __restrict__ dst, int i) {
    float4 v0 = src[i * 2];
    float4 v1 = src[i * 2 + 1];
    __half2 h0 = __floats2half2_rn(v0.x, v0.y);
    __half2 h1 = __floats2half2_rn(v0.z, v0.w);
    __half2 h2 = __floats2half2_rn(v1.x, v1.y);
    __half2 h3 = __floats2half2_rn(v1.z, v1.w);
    uint4 o;
    o.x = *(uint32_t*)&h0; o.y = *(uint32_t*)&h1;
    o.z = *(uint32_t*)&h2; o.w = *(uint32_t*)&h3;
    dst[i] = o;
}

// ---------------- fused prep: routing (block 0) + w1 cvt + x cvt ----------------
__global__ void k_prep(const int* __restrict__ ex,
                       const float4* __restrict__ w1f,
                       const float4* __restrict__ xf)
{
    const int b   = blockIdx.x;
    const int tid = threadIdx.x;

    if (b == 0) {
        __shared__ int s_cnt[NE], s_off[NE + 1], s_cur[NE];
        if (tid < NE) { s_cnt[tid] = 0; s_cur[tid] = 0; }
        __syncthreads();
        for (int i = tid; i < NT; i += blockDim.x)
            atomicAdd(&s_cnt[ex[i]], 1);
        __syncthreads();
        if (tid == 0) {
            int s = 0, nt = 0;
            for (int e = 0; e < NE; e++) {
                s_off[e] = s;
                g_off[e] = s;
                for (int m0 = 0; m0 < s_cnt[e]; m0 += BM) {
                    g_tile_e[nt] = e; g_tile_m[nt] = m0; nt++;
                }
                s += s_cnt[e];
            }
            s_off[NE] = s;
            g_off[NE] = s;
            g_ntiles  = nt;
        }
        __syncthreads();
        for (int i = tid; i < NT; i += blockDim.x) {
            int e = ex[i];
            int r = atomicAdd(&s_cur[e], 1);
            g_perm[s_off[e] + r] = i;
        }
        return;
    }

    if (b <= PREP_W1_BLKS) {
        const int cid = b - 1;
        const int n8  = NE * FD * HD / 8;
        const int stride = PREP_W1_BLKS * 256;
        uint4* dst = (uint4*)g_w1h;
        for (int i = cid * 256 + tid; i < n8; i += stride)
            cvt8(w1f, dst, i);
        return;
    }

    {
        const int cid = b - 1 - PREP_W1_BLKS;
        const int n8  = NT * HD / 8;
        const int stride = PREP_X_BLKS * 256;
        uint4* dst = (uint4*)g_xh;
        for (int i = cid * 256 + tid; i < n8; i += stride)
            cvt8(xf, dst, i);
    }
}

// ---------------- fp16 mma.sync grouped GEMM (512 threads, TMA B fills) ----------------
// FC1: A = gathered g_xh rows (cp.async), B = g_w1h via TMA. -> gelu -> g_hbuf
// FC2: A = g_hbuf rows via TMA, B = g_w2h via TMA. -> gate*atomicAdd -> out
// blockIdx.y < g_ntiles: GEMM m-tile. FC1 blockIdx.y >= MAXT: w2 cvt slices.

template <int KTOT, bool FC1>
__global__ __launch_bounds__(512, 1)
void k_gemm(const __half* __restrict__ Agm,
            const void*   __restrict__ tmapA,
            const void*   __restrict__ tmapB,
            const float*  __restrict__ gate,
            const int*    __restrict__ new_index,
            float*        __restrict__ outp,
            const float*  __restrict__ w2f)
{
    extern __shared__ __align__(1024) char smem[];

    const int tid = threadIdx.x;

    if (FC1 && blockIdx.y >= MAXT) {
        // ---- w2 fp32 -> fp16 conversion slice (scheduled last) ----
        const int  cid    = (blockIdx.y - MAXT) * gridDim.x + blockIdx.x;   // 0..255
        const int  n8     = NE * HD * FD / 8;
        const int  stride = 256 * 512;
        const float4* src = (const float4*)w2f;
        uint4*        dst = (uint4*)g_w2h;
        for (int i = cid * 512 + tid; i < n8; i += stride)
            cvt8(src, dst, i);
        return;
    }

    if ((int)blockIdx.y >= g_ntiles) return;
    const int e    = g_tile_e[blockIdx.y];
    const int m0   = g_tile_m[blockIdx.y];
    const int seg0 = g_off[e];
    const int mlen = g_off[e + 1] - seg0;
    const int n0   = blockIdx.x * BN;

    const int wid = tid >> 5;
    const int lid = tid & 31;
    const int wm  = wid & 1;       // m half (64 rows)
    const int wn  = wid >> 1;      // n slot (32 cols), 0..7

    const uint32_t smem_b = smem_u32(smem);
    const uint32_t mbar0  = smem_b + MBAR_OFF;

    if (tid == 0) {
#pragma unroll
        for (int s = 0; s < STAGES; s++) mbar_init(mbar0 + s * 8, 1);
    }
    __syncthreads();

    // TMA row coordinates
    const int yB = e * (FC1 ? FD : HD) + n0;
    const int yA = seg0 + m0;                 // fc2 only (OOB rows zero-filled)
    const uint32_t expect_bytes = FC1 ? B_STAGE_BYTES : (A_STAGE_BYTES + B_STAGE_BYTES);

    // ---- fc1 A gmem load mapping (cp.async gather) ----
    const int arowL = tid >> 2;
    const int acb   = (tid & 3) * 2;
    const __half* aSrc = nullptr;
    uint32_t offA[2];
    if (FC1) {
        int arow_t = m0 + arowL;
        if (arow_t >= mlen) arow_t = mlen - 1;
        const int arow = g_perm[seg0 + arow_t];
        aSrc = Agm + (size_t)arow * KTOT + acb * 8;
#pragma unroll
        for (int j = 0; j < 2; j++)
            offA[j] = (uint32_t)arowL * 128u + (uint32_t)(((acb + j) ^ (arowL & 7)) << 4);
    }

    // ---- ldmatrix per-lane address components ----
    const int lr  = lid & 7;
    const int lmi = lid >> 3;
    const int rowA0 = wm * 64 + ((lmi & 1) << 3) + lr;
    const int rowB0 = wn * 32 + ((lmi & 1) << 3) + lr;
    const int kHalf = lmi >> 1;
    const int s7A = rowA0 & 7;
    const int s7B = rowB0 & 7;

    float acc[4][4][4];
#pragma unroll
    for (int i = 0; i < 4; i++)
#pragma unroll
        for (int j = 0; j < 4; j++)
#pragma unroll
            for (int q = 0; q < 4; q++) acc[i][j][q] = 0.f;

    const int T = KTOT / BK;

    // fill stage s with k-tile kt (A via cp.async for fc1; A+B via TMA otherwise)
    auto fill = [&](int s, int kt) {
        const uint32_t sa = smem_b + (uint32_t)s * STAGE_BYTES;
        if (FC1) {
            const __half* a = aSrc + kt * BK;
#pragma unroll
            for (int j = 0; j < 2; j++) cp16(sa + offA[j], a + j * 8);
        }
        if (tid == 0) {
            const uint32_t mb = mbar0 + s * 8;
            mbar_expect_tx(mb, expect_bytes);
            if (!FC1) tma_2d(sa, tmapA, kt * BK, yA, mb);
            tma_2d(sa + A_STAGE_BYTES, tmapB, kt * BK, yB, mb);
        }
        cp_commit();
    };

    uint32_t ph[STAGES];
#pragma unroll
    for (int s = 0; s < STAGES; s++) ph[s] = 0;

#pragma unroll
    for (int s = 0; s < STAGES - 1; s++) fill(s, s);

    for (int kt = 0; kt < T; kt++) {
        const int s = kt % STAGES;
        if (FC1) cp_wait<STAGES - 2>();
        mbar_wait(mbar0 + s * 8, ph[s]);
        ph[s] ^= 1;
        __syncthreads();       // all warps done with the stage about to be refilled

        if (kt + STAGES - 1 < T) fill((kt + STAGES - 1) % STAGES, kt + STAGES - 1);

        const uint32_t aBase = smem_b + (uint32_t)s * STAGE_BYTES + (uint32_t)rowA0 * 128u;
        const uint32_t bBase = smem_b + (uint32_t)s * STAGE_BYTES + A_STAGE_BYTES +
                               (uint32_t)rowB0 * 128u;

#pragma unroll
        for (int kk = 0; kk < 4; kk++) {
            const uint32_t swA = (uint32_t)(((2 * kk + kHalf) ^ s7A) << 4);
            const uint32_t swB = (uint32_t)(((2 * kk + kHalf) ^ s7B) << 4);

            uint32_t af[4][4];
#pragma unroll
            for (int fm = 0; fm < 4; fm++)
                ldsm_x4(af[fm], aBase + (uint32_t)fm * 2048u + swA);

            uint32_t bf[2][4];
#pragma unroll
            for (int fn = 0; fn < 2; fn++)
                ldsm_x4(bf[fn], bBase + (uint32_t)fn * 2048u + swB);

#pragma unroll
            for (int fm = 0; fm < 4; fm++)
#pragma unroll
                for (int fn = 0; fn < 2; fn++) {
                    mma_f16(acc[fm][2 * fn + 0], af[fm], bf[fn][0], bf[fn][2]);
                    mma_f16(acc[fm][2 * fn + 1], af[fm], bf[fn][1], bf[fn][3]);
                }
        }
    }

    // ---- epilogue ----
    const int g = lid >> 2;
    const int q = lid & 3;

    if (FC1) {
#pragma unroll
        for (int fm = 0; fm < 4; fm++) {
#pragma unroll
            for (int h = 0; h < 2; h++) {
                const int row = m0 + wm * 64 + fm * 16 + h * 8 + g;
                if (row < mlen) {
                    __half* dst = g_hbuf + (size_t)(seg0 + row) * FD + n0 + wn * 32 + q * 2;
#pragma unroll
                    for (int fn = 0; fn < 4; fn++) {
                        __half2 v = __floats2half2_rn(gelu_exact(acc[fm][fn][h * 2 + 0]),
                                                      gelu_exact(acc[fm][fn][h * 2 + 1]));
                        *(__half2*)(dst + fn * 8) = v;
                    }
                }
            }
        }
    } else {
#pragma unroll
        for (int fm = 0; fm < 4; fm++) {
#pragma unroll
            for (int h = 0; h < 2; h++) {
                const int row = m0 + wm * 64 + fm * 16 + h * 8 + g;
                if (row < mlen) {
                    const int orig = g_perm[seg0 + row];
                    const float gg = gate[orig];
                    const int   dest = new_index[orig] >> 1;
                    float* orow = outp + (size_t)dest * HD + n0 + wn * 32 + q * 2;
#pragma unroll
                    for (int fn = 0; fn < 4; fn++) {
                        atomicAdd(orow + fn * 8 + 0, acc[fm][fn][h * 2 + 0] * gg);
                        atomicAdd(orow + fn * 8 + 1, acc[fm][fn][h * 2 + 1] * gg);
                    }
                }
            }
        }
    }
}

// ---------------- host: tensormap construction ----------------
typedef CUresult (*PFN_encodeTiled)(
    CUtensorMap*, CUtensorMapDataType, cuuint32_t, void*,
    const cuuint64_t*, const cuuint64_t*, const cuuint32_t*, const cuuint32_t*,
    CUtensorMapInterleave, CUtensorMapSwizzle, CUtensorMapL2promotion,
    CUtensorMapFloatOOBfill);

static void build_map(PFN_encodeTiled enc, CUtensorMap* out, void* base,
                      uint64_t d0, uint64_t d1, uint32_t b0, uint32_t b1) {
    cuuint64_t dims[2]    = { d0, d1 };
    cuuint64_t strides[1] = { d0 * 2 };   // bytes per row (fp16)
    cuuint32_t box[2]     = { b0, b1 };
    cuuint32_t es[2]      = { 1, 1 };
    enc(out, CU_TENSOR_MAP_DATA_TYPE_FLOAT16, 2, base, dims, strides, box, es,
        CU_TENSOR_MAP_INTERLEAVE_NONE, CU_TENSOR_MAP_SWIZZLE_128B,
        CU_TENSOR_MAP_L2_PROMOTION_L2_128B, CU_TENSOR_MAP_FLOAT_OOB_FILL_NONE);
}

// ---------------- launch ----------------
extern "C" void kernel_launch(void* const* d_in, const int* in_sizes, int n_in,
                              void* d_out, int out_size) {
    const float* x         = (const float*)d_in[0];
    const float* gate      = (const float*)d_in[1];
    const int*   experts   = (const int*)  d_in[2];
    const int*   new_index = (const int*)  d_in[3];
    const float* w1        = (const float*)d_in[4];
    const float* w2        = (const float*)d_in[5];
    float*       out       = (float*)d_out;

    cudaFuncSetAttribute(k_gemm<HD, true>,  cudaFuncAttributeMaxDynamicSharedMemorySize, SMEM_BYTES);
    cudaFuncSetAttribute(k_gemm<FD, false>, cudaFuncAttributeMaxDynamicSharedMemorySize, SMEM_BYTES);

    __half* w1h; __half* w2h; __half* xh; __half* hbuf;
    unsigned char* tmaps_d;
    cudaGetSymbolAddress((void**)&w1h,    g_w1h);
    cudaGetSymbolAddress((void**)&w2h,    g_w2h);
    cudaGetSymbolAddress((void**)&xh,     g_xh);
    cudaGetSymbolAddress((void**)&hbuf,   g_hbuf);
    cudaGetSymbolAddress((void**)&tmaps_d, g_tmaps);

    // build tensormaps (host-side, deterministic every call)
    static __align__(128) unsigned char h_tmaps[3 * 128];
    PFN_encodeTiled enc = nullptr;
    cudaDriverEntryPointQueryResult qr;
    cudaGetDriverEntryPoint("cuTensorMapEncodeTiled", (void**)&enc,
                            cudaEnableDefault, &qr);
    build_map(enc, (CUtensorMap*)(h_tmaps + 0),   w1h,  HD, (uint64_t)NE * FD, BK, BN);
    build_map(enc, (CUtensorMap*)(h_tmaps + 128), w2h,  FD, (uint64_t)NE * HD, BK, BN);
    build_map(enc, (CUtensorMap*)(h_tmaps + 256), hbuf, FD, (uint64_t)NT,      BK, BM);
    cudaMemcpyAsync(tmaps_d, h_tmaps, sizeof(h_tmaps), cudaMemcpyHostToDevice, 0);

    cudaMemsetAsync(d_out, 0, (size_t)out_size * sizeof(float), 0);

    // fused prep: block 0 routing; blocks 1..4096 w1 cvt; 4097..5120 x cvt
    k_prep<<<1 + PREP_W1_BLKS + PREP_X_BLKS, 256>>>(
        experts, (const float4*)w1, (const float4*)x);

    // fc1: gelu(x @ w1^T) -> g_hbuf; + 16 trailing y-blocks convert w2 -> g_w2h
    k_gemm<HD, true><<<dim3(FD / BN, MAXT + 16), 512, SMEM_BYTES>>>(
        xh, nullptr, tmaps_d + 0, gate, new_index, out, w2);
    // fc2: (hbuf @ w2^T) * gate -> atomicAdd topk-scatter
    k_gemm<FD, false><<<dim3(HD / BN, MAXT), 512, SMEM_BYTES>>>(
        nullptr, tmaps_d + 256, tmaps_d + 128, gate, new_index, out, nullptr);
}

// round 16
// speedup vs baseline: 1.3847x; 1.0096x over previous
#include <cuda_runtime.h>
#include <cuda.h>
#include <cuda_fp16.h>
#include <math.h>
#include <stdint.h>

// ---------------- problem constants ----------------
#define NE 8
#define HD 1024
#define FD 4096
#define NT 8192
#define MAXT 72                                  // max live m-tiles

// ---------------- GEMM tile config (fp16, m16n8k16), 512 threads ----------------
#define BM 128
#define BN 256
#define BK 64                                    // 64 halves = 128B row
#define STAGES 4
#define A_STAGE_BYTES (BM * BK * 2)              // 16384
#define B_STAGE_BYTES (BN * BK * 2)              // 32768
#define STAGE_BYTES   (A_STAGE_BYTES + B_STAGE_BYTES)   // 49152
#define MBAR_OFF      (STAGES * STAGE_BYTES)            // 196608
#define SMEM_BYTES    (MBAR_OFF + 64)

// prep kernel block ranges
#define PREP_W1_BLKS 4096
#define PREP_X_BLKS  1024

// ---------------- device scratch ----------------
__device__ __align__(128) __half g_w1h[(size_t)NE * FD * HD];
__device__ __align__(128) __half g_w2h[(size_t)NE * HD * FD];
__device__ __align__(128) __half g_xh[(size_t)NT * HD];    // fp16 x, GATHERED (sorted) order
__device__ __align__(128) __half g_hbuf[(size_t)NT * FD];  // gelu(fc1), sorted order
__device__ __align__(128) unsigned char g_tmaps[4 * 128];  // 0: w1, 1: w2, 2: hbuf, 3: xs
__device__ int g_perm[NT];
__device__ int g_off[NE + 1];
__device__ int g_tile_e[MAXT], g_tile_m[MAXT], g_ntiles;

// ---------------- helpers ----------------
__device__ __forceinline__ uint32_t smem_u32(const void* p) {
    uint32_t a;
    asm("{ .reg .u64 t; cvta.to.shared.u64 t, %1; cvt.u32.u64 %0, t; }" : "=r"(a) : "l"(p));
    return a;
}
__device__ __forceinline__ void mbar_init(uint32_t mbar, uint32_t cnt) {
    asm volatile("mbarrier.init.shared.b64 [%0], %1;" :: "r"(mbar), "r"(cnt) : "memory");
}
__device__ __forceinline__ void mbar_expect_tx(uint32_t mbar, uint32_t bytes) {
    asm volatile("mbarrier.arrive.expect_tx.shared.b64 _, [%0], %1;"
                 :: "r"(mbar), "r"(bytes) : "memory");
}
__device__ __forceinline__ void mbar_wait(uint32_t mbar, uint32_t phase) {
    asm volatile(
        "{\n\t.reg .pred P;\n\t"
        "W_%=:\n\t"
        "mbarrier.try_wait.parity.shared.b64 P, [%0], %1;\n\t"
        "@P bra.uni D_%=;\n\t"
        "bra.uni W_%=;\n\t"
        "D_%=:\n\t}"
        :: "r"(mbar), "r"(phase) : "memory");
}
__device__ __forceinline__ void tma_2d(uint32_t smem_dst, const void* tmap,
                                       int x, int y, uint32_t mbar) {
    asm volatile(
        "cp.async.bulk.tensor.2d.shared::cta.global.tile.mbarrier::complete_tx::bytes "
        "[%0], [%1, {%2, %3}], [%4];"
        :: "r"(smem_dst), "l"(tmap), "r"(x), "r"(y), "r"(mbar) : "memory");
}
__device__ __forceinline__ void ldsm_x4(uint32_t* r, uint32_t addr) {
    asm volatile("ldmatrix.sync.aligned.m8n8.x4.shared.b16 {%0,%1,%2,%3}, [%4];"
                 : "=r"(r[0]), "=r"(r[1]), "=r"(r[2]), "=r"(r[3]) : "r"(addr));
}
__device__ __forceinline__ void mma_f16(float* c, const uint32_t* a, uint32_t b0, uint32_t b1) {
    asm volatile(
        "mma.sync.aligned.m16n8k16.row.col.f32.f16.f16.f32 "
        "{%0,%1,%2,%3}, {%4,%5,%6,%7}, {%8,%9}, {%0,%1,%2,%3};"
        : "+f"(c[0]), "+f"(c[1]), "+f"(c[2]), "+f"(c[3])
        : "r"(a[0]), "r"(a[1]), "r"(a[2]), "r"(a[3]), "r"(b0), "r"(b1));
}
__device__ __forceinline__ float gelu_exact(float v) {
    return 0.5f * v * (1.0f + erff(v * 0.7071067811865476f));
}
__device__ __forceinline__ void cvt8(const float4* __restrict__ src, uint4* __restrict__ dst,
                                     long isrc, long idst) {
    float4 v0 = src[isrc * 2];
    float4 v1 = src[isrc * 2 + 1];
    __half2 h0 = __floats2half2_rn(v0.x, v0.y);
    __half2 h1 = __floats2half2_rn(v0.z, v0.w);
    __half2 h2 = __floats2half2_rn(v1.x, v1.y);
    __half2 h3 = __floats2half2_rn(v1.z, v1.w);
    uint4 o;
    o.x = *(uint32_t*)&h0; o.y = *(uint32_t*)&h1;
    o.z = *(uint32_t*)&h2; o.w = *(uint32_t*)&h3;
    dst[idst] = o;
}

// ---------------- routing: single block (runs before prep gather) ----------------
__global__ void k_route(const int* __restrict__ ex) {
    const int tid = threadIdx.x;
    __shared__ int s_cnt[NE], s_off[NE + 1], s_cur[NE];
    if (tid < NE) { s_cnt[tid] = 0; s_cur[tid] = 0; }
    __syncthreads();
    for (int i = tid; i < NT; i += blockDim.x)
        atomicAdd(&s_cnt[ex[i]], 1);
    __syncthreads();
    if (tid == 0) {
        int s = 0, nt = 0;
        for (int e = 0; e < NE; e++) {
            s_off[e] = s;
            g_off[e] = s;
            for (int m0 = 0; m0 < s_cnt[e]; m0 += BM) {
                g_tile_e[nt] = e; g_tile_m[nt] = m0; nt++;
            }
            s += s_cnt[e];
        }
        s_off[NE] = s;
        g_off[NE] = s;
        g_ntiles  = nt;
    }
    __syncthreads();
    for (int i = tid; i < NT; i += blockDim.x) {
        int e = ex[i];
        int r = atomicAdd(&s_cur[e], 1);
        g_perm[s_off[e] + r] = i;
    }
}

// ---------------- prep: w1 cvt + x gather-cvt (needs g_perm) ----------------
__global__ void k_prep(const float4* __restrict__ w1f,
                       const float4* __restrict__ xf)
{
    const int b   = blockIdx.x;
    const int tid = threadIdx.x;

    if (b < PREP_W1_BLKS) {
        const int n8  = NE * FD * HD / 8;
        const int stride = PREP_W1_BLKS * 256;
        uint4* dst = (uint4*)g_w1h;
        for (int i = b * 256 + tid; i < n8; i += stride)
            cvt8(w1f, dst, i, i);
        return;
    }

    // x gather + cvt: g_xh[row] = fp16(x[g_perm[row]])  (rows are 4KB contiguous)
    {
        const int cid = b - PREP_W1_BLKS;
        const int n8  = NT * HD / 8;            // uint4 units, dst-indexed
        const int stride = PREP_X_BLKS * 256;
        const int rw = HD / 8;                  // units per row (128)
        uint4* dst = (uint4*)g_xh;
        for (int i = cid * 256 + tid; i < n8; i += stride) {
            const int row = i / rw;
            const int col = i - row * rw;
            cvt8(xf, dst, (long)g_perm[row] * rw + col, i);
        }
    }
}

// ---------------- fp16 mma.sync grouped GEMM (512 threads, full TMA fills) ----------------
// FC1: A = g_xh (sorted) via TMA, B = g_w1h via TMA -> gelu -> g_hbuf
// FC2: A = g_hbuf via TMA,        B = g_w2h via TMA -> gate*atomicAdd -> out
// blockIdx.y < g_ntiles: GEMM m-tile. FC1 blockIdx.y >= MAXT: w2 cvt slices.

template <int KTOT, bool FC1>
__global__ __launch_bounds__(512, 1)
void k_gemm(const void*   __restrict__ tmapA,
            const void*   __restrict__ tmapB,
            const float*  __restrict__ gate,
            const int*    __restrict__ new_index,
            float*        __restrict__ outp,
            const float*  __restrict__ w2f)
{
    extern __shared__ __align__(1024) char smem[];

    const int tid = threadIdx.x;

    if (FC1 && blockIdx.y >= MAXT) {
        // ---- w2 fp32 -> fp16 conversion slice (scheduled last) ----
        const int  cid    = (blockIdx.y - MAXT) * gridDim.x + blockIdx.x;   // 0..255
        const int  n8     = NE * HD * FD / 8;
        const int  stride = 256 * 512;
        const float4* src = (const float4*)w2f;
        uint4*        dst = (uint4*)g_w2h;
        for (int i = cid * 512 + tid; i < n8; i += stride)
            cvt8(src, dst, i, i);
        return;
    }

    if ((int)blockIdx.y >= g_ntiles) return;
    const int e    = g_tile_e[blockIdx.y];
    const int m0   = g_tile_m[blockIdx.y];
    const int seg0 = g_off[e];
    const int mlen = g_off[e + 1] - seg0;
    const int n0   = blockIdx.x * BN;

    const int wid = tid >> 5;
    const int lid = tid & 31;
    const int wm  = wid & 1;       // m half (64 rows)
    const int wn  = wid >> 1;      // n slot (32 cols), 0..7

    const uint32_t smem_b = smem_u32(smem);
    const uint32_t mbar0  = smem_b + MBAR_OFF;

    if (tid == 0) {
#pragma unroll
        for (int s = 0; s < STAGES; s++) mbar_init(mbar0 + s * 8, 1);
    }
    __syncthreads();

    // TMA row coordinates
    const int yB = e * (FC1 ? FD : HD) + n0;
    const int yA = seg0 + m0;                 // sorted-order A rows (OOB -> junk, masked)

    // ---- ldmatrix per-lane address components ----
    const int lr  = lid & 7;
    const int lmi = lid >> 3;
    const int rowA0 = wm * 64 + ((lmi & 1) << 3) + lr;
    const int rowB0 = wn * 32 + ((lmi & 1) << 3) + lr;
    const int kHalf = lmi >> 1;
    const int s7A = rowA0 & 7;
    const int s7B = rowB0 & 7;

    float acc[4][4][4];
#pragma unroll
    for (int i = 0; i < 4; i++)
#pragma unroll
        for (int j = 0; j < 4; j++)
#pragma unroll
            for (int q = 0; q < 4; q++) acc[i][j][q] = 0.f;

    const int T = KTOT / BK;

    auto fill = [&](int s, int kt) {
        if (tid == 0) {
            const uint32_t sa = smem_b + (uint32_t)s * STAGE_BYTES;
            const uint32_t mb = mbar0 + s * 8;
            mbar_expect_tx(mb, A_STAGE_BYTES + B_STAGE_BYTES);
            tma_2d(sa,                 tmapA, kt * BK, yA, mb);
            tma_2d(sa + A_STAGE_BYTES, tmapB, kt * BK, yB, mb);
        }
    };

    uint32_t ph[STAGES];
#pragma unroll
    for (int s = 0; s < STAGES; s++) ph[s] = 0;

#pragma unroll
    for (int s = 0; s < STAGES - 1; s++) fill(s, s);

    for (int kt = 0; kt < T; kt++) {
        const int s = kt % STAGES;
        mbar_wait(mbar0 + s * 8, ph[s]);
        ph[s] ^= 1;
        __syncthreads();       // all warps done with the stage about to be refilled

        if (kt + STAGES - 1 < T) fill((kt + STAGES - 1) % STAGES, kt + STAGES - 1);

        const uint32_t aBase = smem_b + (uint32_t)s * STAGE_BYTES + (uint32_t)rowA0 * 128u;
        const uint32_t bBase = smem_b + (uint32_t)s * STAGE_BYTES + A_STAGE_BYTES +
                               (uint32_t)rowB0 * 128u;

#pragma unroll
        for (int kk = 0; kk < 4; kk++) {
            const uint32_t swA = (uint32_t)(((2 * kk + kHalf) ^ s7A) << 4);
            const uint32_t swB = (uint32_t)(((2 * kk + kHalf) ^ s7B) << 4);

            uint32_t af[4][4];
#pragma unroll
            for (int fm = 0; fm < 4; fm++)
                ldsm_x4(af[fm], aBase + (uint32_t)fm * 2048u + swA);

            uint32_t bf[2][4];
#pragma unroll
            for (int fn = 0; fn < 2; fn++)
                ldsm_x4(bf[fn], bBase + (uint32_t)fn * 2048u + swB);

#pragma unroll
            for (int fm = 0; fm < 4; fm++)
#pragma unroll
                for (int fn = 0; fn < 2; fn++) {
                    mma_f16(acc[fm][2 * fn + 0], af[fm], bf[fn][0], bf[fn][2]);
                    mma_f16(acc[fm][2 * fn + 1], af[fm], bf[fn][1], bf[fn][3]);
                }
        }
    }

    // ---- epilogue ----
    const int g = lid >> 2;
    const int q = lid & 3;

    if (FC1) {
#pragma unroll
        for (int fm = 0; fm < 4; fm++) {
#pragma unroll
            for (int h = 0; h < 2; h++) {
                const int row = m0 + wm * 64 + fm * 16 + h * 8 + g;
                if (row < mlen) {
                    __half* dst = g_hbuf + (size_t)(seg0 + row) * FD + n0 + wn * 32 + q * 2;
#pragma unroll
                    for (int fn = 0; fn < 4; fn++) {
                        __half2 v = __floats2half2_rn(gelu_exact(acc[fm][fn][h * 2 + 0]),
                                                      gelu_exact(acc[fm][fn][h * 2 + 1]));
                        *(__half2*)(dst + fn * 8) = v;
                    }
                }
            }
        }
    } else {
#pragma unroll
        for (int fm = 0; fm < 4; fm++) {
#pragma unroll
            for (int h = 0; h < 2; h++) {
                const int row = m0 + wm * 64 + fm * 16 + h * 8 + g;
                if (row < mlen) {
                    const int orig = g_perm[seg0 + row];
                    const float gg = gate[orig];
                    const int   dest = new_index[orig] >> 1;
                    float* orow = outp + (size_t)dest * HD + n0 + wn * 32 + q * 2;
#pragma unroll
                    for (int fn = 0; fn < 4; fn++) {
                        atomicAdd(orow + fn * 8 + 0, acc[fm][fn][h * 2 + 0] * gg);
                        atomicAdd(orow + fn * 8 + 1, acc[fm][fn][h * 2 + 1] * gg);
                    }
                }
            }
        }
    }
}

// ---------------- host: tensormap construction ----------------
typedef CUresult (*PFN_encodeTiled)(
    CUtensorMap*, CUtensorMapDataType, cuuint32_t, void*,
    const cuuint64_t*, const cuuint64_t*, const cuuint32_t*, const cuuint32_t*,
    CUtensorMapInterleave, CUtensorMapSwizzle, CUtensorMapL2promotion,
    CUtensorMapFloatOOBfill);

static void build_map(PFN_encodeTiled enc, CUtensorMap* out, void* base,
                      uint64_t d0, uint64_t d1, uint32_t b0, uint32_t b1) {
    cuuint64_t dims[2]    = { d0, d1 };
    cuuint64_t strides[1] = { d0 * 2 };   // bytes per row (fp16)
    cuuint32_t box[2]     = { b0, b1 };
    cuuint32_t es[2]      = { 1, 1 };
    enc(out, CU_TENSOR_MAP_DATA_TYPE_FLOAT16, 2, base, dims, strides, box, es,
        CU_TENSOR_MAP_INTERLEAVE_NONE, CU_TENSOR_MAP_SWIZZLE_128B,
        CU_TENSOR_MAP_L2_PROMOTION_L2_128B, CU_TENSOR_MAP_FLOAT_OOB_FILL_NONE);
}

// ---------------- launch ----------------
extern "C" void kernel_launch(void* const* d_in, const int* in_sizes, int n_in,
                              void* d_out, int out_size) {
    const float* x         = (const float*)d_in[0];
    const float* gate      = (const float*)d_in[1];
    const int*   experts   = (const int*)  d_in[2];
    const int*   new_index = (const int*)  d_in[3];
    const float* w1        = (const float*)d_in[4];
    const float* w2        = (const float*)d_in[5];
    float*       out       = (float*)d_out;

    cudaFuncSetAttribute(k_gemm<HD, true>,  cudaFuncAttributeMaxDynamicSharedMemorySize, SMEM_BYTES);
    cudaFuncSetAttribute(k_gemm<FD, false>, cudaFuncAttributeMaxDynamicSharedMemorySize, SMEM_BYTES);

    __half* w1h; __half* w2h; __half* xh; __half* hbuf;
    unsigned char* tmaps_d;
    cudaGetSymbolAddress((void**)&w1h,    g_w1h);
    cudaGetSymbolAddress((void**)&w2h,    g_w2h);
    cudaGetSymbolAddress((void**)&xh,     g_xh);
    cudaGetSymbolAddress((void**)&hbuf,   g_hbuf);
    cudaGetSymbolAddress((void**)&tmaps_d, g_tmaps);

    // build tensormaps (host-side, deterministic every call)
    static __align__(128) unsigned char h_tmaps[4 * 128];
    PFN_encodeTiled enc = nullptr;
    cudaDriverEntryPointQueryResult qr;
    cudaGetDriverEntryPoint("cuTensorMapEncodeTiled", (void**)&enc,
                            cudaEnableDefault, &qr);
    build_map(enc, (CUtensorMap*)(h_tmaps + 0),   w1h,  HD, (uint64_t)NE * FD, BK, BN);
    build_map(enc, (CUtensorMap*)(h_tmaps + 128), w2h,  FD, (uint64_t)NE * HD, BK, BN);
    build_map(enc, (CUtensorMap*)(h_tmaps + 256), hbuf, FD, (uint64_t)NT,      BK, BM);
    build_map(enc, (CUtensorMap*)(h_tmaps + 384), xh,   HD, (uint64_t)NT,      BK, BM);
    cudaMemcpyAsync(tmaps_d, h_tmaps, sizeof(h_tmaps), cudaMemcpyHostToDevice, 0);

    cudaMemsetAsync(d_out, 0, (size_t)out_size * sizeof(float), 0);

    // routing first (g_perm needed by the x gather in k_prep)
    k_route<<<1, 256>>>(experts);
    // prep: blocks 0..4095 w1 cvt; 4096..5119 x gather+cvt (sorted order)
    k_prep<<<PREP_W1_BLKS + PREP_X_BLKS, 256>>>(
        (const float4*)w1, (const float4*)x);

    // fc1: gelu(xs @ w1^T) -> g_hbuf; + 16 trailing y-blocks convert w2 -> g_w2h
    k_gemm<HD, true><<<dim3(FD / BN, MAXT + 16), 512, SMEM_BYTES>>>(
        tmaps_d + 384, tmaps_d + 0, gate, new_index, out, w2);
    // fc2: (hbuf @ w2^T) * gate -> atomicAdd topk-scatter
    k_gemm<FD, false><<<dim3(HD / BN, MAXT), 512, SMEM_BYTES>>>(
        tmaps_d + 256, tmaps_d + 128, gate, new_index, out, nullptr);
}

// round 17
// speedup vs baseline: 1.4802x; 1.0690x over previous
#include <cuda_runtime.h>
#include <cuda.h>
#include <cuda_fp16.h>
#include <math.h>
#include <stdint.h>

// ---------------- problem constants ----------------
#define NE 8
#define HD 1024
#define FD 4096
#define NT 8192
#define MAXT 72                                  // max live m-tiles

// ---------------- GEMM tile config (fp16, m16n8k16), 512 threads ----------------
#define BM 128
#define BN 256
#define BK 64                                    // 64 halves = 128B row
#define STAGES 4
#define A_STAGE_BYTES (BM * BK * 2)              // 16384
#define B_STAGE_BYTES (BN * BK * 2)              // 32768
#define STAGE_BYTES   (A_STAGE_BYTES + B_STAGE_BYTES)   // 49152
#define MBAR_OFF      (STAGES * STAGE_BYTES)            // 196608
#define SMEM_BYTES    (MBAR_OFF + 128)

// prep kernel block ranges
#define PREP_W1_BLKS 4096
#define PREP_X_BLKS  1024

// ---------------- device scratch ----------------
__device__ __align__(128) __half g_w1h[(size_t)NE * FD * HD];
__device__ __align__(128) __half g_w2h[(size_t)NE * HD * FD];
__device__ __align__(128) __half g_xh[(size_t)NT * HD];    // fp16 x, GATHERED (sorted) order
__device__ __align__(128) __half g_hbuf[(size_t)NT * FD];  // gelu(fc1), sorted order
__device__ __align__(128) unsigned char g_tmaps[4 * 128];  // 0: w1, 1: w2, 2: hbuf, 3: xs
__device__ int g_perm[NT];
__device__ int g_off[NE + 1];
__device__ int g_tile_e[MAXT], g_tile_m[MAXT], g_ntiles;

// ---------------- helpers ----------------
__device__ __forceinline__ uint32_t smem_u32(const void* p) {
    uint32_t a;
    asm("{ .reg .u64 t; cvta.to.shared.u64 t, %1; cvt.u32.u64 %0, t; }" : "=r"(a) : "l"(p));
    return a;
}
__device__ __forceinline__ void mbar_init(uint32_t mbar, uint32_t cnt) {
    asm volatile("mbarrier.init.shared.b64 [%0], %1;" :: "r"(mbar), "r"(cnt) : "memory");
}
__device__ __forceinline__ void mbar_arrive(uint32_t mbar) {
    asm volatile("mbarrier.arrive.shared.b64 _, [%0];" :: "r"(mbar) : "memory");
}
__device__ __forceinline__ void mbar_expect_tx(uint32_t mbar, uint32_t bytes) {
    asm volatile("mbarrier.arrive.expect_tx.shared.b64 _, [%0], %1;"
                 :: "r"(mbar), "r"(bytes) : "memory");
}
__device__ __forceinline__ void mbar_wait(uint32_t mbar, uint32_t phase) {
    asm volatile(
        "{\n\t.reg .pred P;\n\t"
        "W_%=:\n\t"
        "mbarrier.try_wait.parity.shared.b64 P, [%0], %1;\n\t"
        "@P bra.uni D_%=;\n\t"
        "bra.uni W_%=;\n\t"
        "D_%=:\n\t}"
        :: "r"(mbar), "r"(phase) : "memory");
}
__device__ __forceinline__ void tma_2d(uint32_t smem_dst, const void* tmap,
                                       int x, int y, uint32_t mbar) {
    asm volatile(
        "cp.async.bulk.tensor.2d.shared::cta.global.tile.mbarrier::complete_tx::bytes "
        "[%0], [%1, {%2, %3}], [%4];"
        :: "r"(smem_dst), "l"(tmap), "r"(x), "r"(y), "r"(mbar) : "memory");
}
__device__ __forceinline__ void ldsm_x4(uint32_t* r, uint32_t addr) {
    asm volatile("ldmatrix.sync.aligned.m8n8.x4.shared.b16 {%0,%1,%2,%3}, [%4];"
                 : "=r"(r[0]), "=r"(r[1]), "=r"(r[2]), "=r"(r[3]) : "r"(addr));
}
__device__ __forceinline__ void mma_f16(float* c, const uint32_t* a, uint32_t b0, uint32_t b1) {
    asm volatile(
        "mma.sync.aligned.m16n8k16.row.col.f32.f16.f16.f32 "
        "{%0,%1,%2,%3}, {%4,%5,%6,%7}, {%8,%9}, {%0,%1,%2,%3};"
        : "+f"(c[0]), "+f"(c[1]), "+f"(c[2]), "+f"(c[3])
        : "r"(a[0]), "r"(a[1]), "r"(a[2]), "r"(a[3]), "r"(b0), "r"(b1));
}
__device__ __forceinline__ float gelu_exact(float v) {
    return 0.5f * v * (1.0f + erff(v * 0.7071067811865476f));
}
__device__ __forceinline__ void cvt8(const float4* __restrict__ src, uint4* __restrict__ dst,
                                     long isrc, long idst) {
    float4 v0 = src[isrc * 2];
    float4 v1 = src[isrc * 2 + 1];
    __half2 h0 = __floats2half2_rn(v0.x, v0.y);
    __half2 h1 = __floats2half2_rn(v0.z, v0.w);
    __half2 h2 = __floats2half2_rn(v1.x, v1.y);
    __half2 h3 = __floats2half2_rn(v1.z, v1.w);
    uint4 o;
    o.x = *(uint32_t*)&h0; o.y = *(uint32_t*)&h1;
    o.z = *(uint32_t*)&h2; o.w = *(uint32_t*)&h3;
    dst[idst] = o;
}

// ---------------- routing: single block (runs before prep gather) ----------------
__global__ void k_route(const int* __restrict__ ex) {
    const int tid = threadIdx.x;
    __shared__ int s_cnt[NE], s_off[NE + 1], s_cur[NE];
    if (tid < NE) { s_cnt[tid] = 0; s_cur[tid] = 0; }
    __syncthreads();
    for (int i = tid; i < NT; i += blockDim.x)
        atomicAdd(&s_cnt[ex[i]], 1);
    __syncthreads();
    if (tid == 0) {
        int s = 0, nt = 0;
        for (int e = 0; e < NE; e++) {
            s_off[e] = s;
            g_off[e] = s;
            for (int m0 = 0; m0 < s_cnt[e]; m0 += BM) {
                g_tile_e[nt] = e; g_tile_m[nt] = m0; nt++;
            }
            s += s_cnt[e];
        }
        s_off[NE] = s;
        g_off[NE] = s;
        g_ntiles  = nt;
    }
    __syncthreads();
    for (int i = tid; i < NT; i += blockDim.x) {
        int e = ex[i];
        int r = atomicAdd(&s_cur[e], 1);
        g_perm[s_off[e] + r] = i;
    }
}

// ---------------- prep: w1 cvt + x gather-cvt (needs g_perm) ----------------
__global__ void k_prep(const float4* __restrict__ w1f,
                       const float4* __restrict__ xf)
{
    const int b   = blockIdx.x;
    const int tid = threadIdx.x;

    if (b < PREP_W1_BLKS) {
        const int n8  = NE * FD * HD / 8;
        const int stride = PREP_W1_BLKS * 256;
        uint4* dst = (uint4*)g_w1h;
        for (int i = b * 256 + tid; i < n8; i += stride)
            cvt8(w1f, dst, i, i);
        return;
    }

    // x gather + cvt: g_xh[row] = fp16(x[g_perm[row]])  (rows are 4KB contiguous)
    {
        const int cid = b - PREP_W1_BLKS;
        const int n8  = NT * HD / 8;            // uint4 units, dst-indexed
        const int stride = PREP_X_BLKS * 256;
        const int rw = HD / 8;                  // units per row (128)
        uint4* dst = (uint4*)g_xh;
        for (int i = cid * 256 + tid; i < n8; i += stride) {
            const int row = i / rw;
            const int col = i - row * rw;
            cvt8(xf, dst, (long)g_perm[row] * rw + col, i);
        }
    }
}

// ---------------- fp16 mma.sync grouped GEMM ----------------
// 512 threads, full TMA fills, producer/consumer mbarrier pipeline (no
// __syncthreads in the mainloop): full[s] = TMA tx barrier (count 1);
// empty[s] = consumer barrier (count 16, one arrive per warp). Only warp 0
// (producer) waits on empty; warps drift up to STAGES-1 ktiles apart.

template <int KTOT, bool FC1>
__global__ __launch_bounds__(512, 1)
void k_gemm(const void*   __restrict__ tmapA,
            const void*   __restrict__ tmapB,
            const float*  __restrict__ gate,
            const int*    __restrict__ new_index,
            float*        __restrict__ outp,
            const float*  __restrict__ w2f)
{
    extern __shared__ __align__(1024) char smem[];

    const int tid = threadIdx.x;

    if (FC1 && blockIdx.y >= MAXT) {
        // ---- w2 fp32 -> fp16 conversion slice (scheduled last) ----
        const int  cid    = (blockIdx.y - MAXT) * gridDim.x + blockIdx.x;   // 0..255
        const int  n8     = NE * HD * FD / 8;
        const int  stride = 256 * 512;
        const float4* src = (const float4*)w2f;
        uint4*        dst = (uint4*)g_w2h;
        for (int i = cid * 512 + tid; i < n8; i += stride)
            cvt8(src, dst, i, i);
        return;
    }

    if ((int)blockIdx.y >= g_ntiles) return;
    const int e    = g_tile_e[blockIdx.y];
    const int m0   = g_tile_m[blockIdx.y];
    const int seg0 = g_off[e];
    const int mlen = g_off[e + 1] - seg0;
    const int n0   = blockIdx.x * BN;

    const int wid = tid >> 5;
    const int lid = tid & 31;
    const int wm  = wid & 1;       // m half (64 rows)
    const int wn  = wid >> 1;      // n slot (32 cols), 0..7

    const uint32_t smem_b = smem_u32(smem);
    const uint32_t fullb  = smem_b + MBAR_OFF;        // 4 x 8B
    const uint32_t emptyb = smem_b + MBAR_OFF + 32;   // 4 x 8B

    if (tid == 0) {
#pragma unroll
        for (int s = 0; s < STAGES; s++) {
            mbar_init(fullb  + s * 8, 1);
            mbar_init(emptyb + s * 8, 16);
        }
    }
    __syncthreads();   // once, before the pipeline starts

    // TMA row coordinates
    const int yB = e * (FC1 ? FD : HD) + n0;
    const int yA = seg0 + m0;                 // sorted-order A rows (OOB -> junk, masked)

    // ---- ldmatrix per-lane address components ----
    const int lr  = lid & 7;
    const int lmi = lid >> 3;
    const int rowA0 = wm * 64 + ((lmi & 1) << 3) + lr;
    const int rowB0 = wn * 32 + ((lmi & 1) << 3) + lr;
    const int kHalf = lmi >> 1;
    const int s7A = rowA0 & 7;
    const int s7B = rowB0 & 7;

    float acc[4][4][4];
#pragma unroll
    for (int i = 0; i < 4; i++)
#pragma unroll
        for (int j = 0; j < 4; j++)
#pragma unroll
            for (int q = 0; q < 4; q++) acc[i][j][q] = 0.f;

    const int T = KTOT / BK;

    auto fill = [&](int s, int kt) {
        const uint32_t sa = smem_b + (uint32_t)s * STAGE_BYTES;
        const uint32_t mb = fullb + s * 8;
        mbar_expect_tx(mb, A_STAGE_BYTES + B_STAGE_BYTES);
        tma_2d(sa,                 tmapA, kt * BK, yA, mb);
        tma_2d(sa + A_STAGE_BYTES, tmapB, kt * BK, yB, mb);
    };

    uint32_t fph[STAGES] = {0, 0, 0, 0};
    uint32_t eph[STAGES] = {0, 0, 0, 0};   // producer (tid 0) only

    if (tid == 0) {
#pragma unroll
        for (int s = 0; s < STAGES - 1; s++) fill(s, s);
    }

    for (int kt = 0; kt < T; kt++) {
        const int s = kt % STAGES;
        mbar_wait(fullb + s * 8, fph[s]);
        fph[s] ^= 1;

        // producer: refill the stage that ktile kt-1 just vacated
        if (tid == 0 && kt + STAGES - 1 < T) {
            const int s3 = (kt + STAGES - 1) % STAGES;
            if (kt >= 1) { mbar_wait(emptyb + s3 * 8, eph[s3]); eph[s3] ^= 1; }
            fill(s3, kt + STAGES - 1);
        }

        const uint32_t aBase = smem_b + (uint32_t)s * STAGE_BYTES + (uint32_t)rowA0 * 128u;
        const uint32_t bBase = smem_b + (uint32_t)s * STAGE_BYTES + A_STAGE_BYTES +
                               (uint32_t)rowB0 * 128u;

#pragma unroll
        for (int kk = 0; kk < 4; kk++) {
            const uint32_t swA = (uint32_t)(((2 * kk + kHalf) ^ s7A) << 4);
            const uint32_t swB = (uint32_t)(((2 * kk + kHalf) ^ s7B) << 4);

            uint32_t af[4][4];
#pragma unroll
            for (int fm = 0; fm < 4; fm++)
                ldsm_x4(af[fm], aBase + (uint32_t)fm * 2048u + swA);

            uint32_t bf[2][4];
#pragma unroll
            for (int fn = 0; fn < 2; fn++)
                ldsm_x4(bf[fn], bBase + (uint32_t)fn * 2048u + swB);

#pragma unroll
            for (int fm = 0; fm < 4; fm++)
#pragma unroll
                for (int fn = 0; fn < 2; fn++) {
                    mma_f16(acc[fm][2 * fn + 0], af[fm], bf[fn][0], bf[fn][2]);
                    mma_f16(acc[fm][2 * fn + 1], af[fm], bf[fn][1], bf[fn][3]);
                }
        }

        // consumer: this warp is done reading stage s
        if (lid == 0) mbar_arrive(emptyb + s * 8);
    }

    // ---- epilogue ----
    const int g = lid >> 2;
    const int q = lid & 3;

    if (FC1) {
#pragma unroll
        for (int fm = 0; fm < 4; fm++) {
#pragma unroll
            for (int h = 0; h < 2; h++) {
                const int row = m0 + wm * 64 + fm * 16 + h * 8 + g;
                if (row < mlen) {
                    __half* dst = g_hbuf + (size_t)(seg0 + row) * FD + n0 + wn * 32 + q * 2;
#pragma unroll
                    for (int fn = 0; fn < 4; fn++) {
                        __half2 v = __floats2half2_rn(gelu_exact(acc[fm][fn][h * 2 + 0]),
                                                      gelu_exact(acc[fm][fn][h * 2 + 1]));
                        *(__half2*)(dst + fn * 8) = v;
                    }
                }
            }
        }
    } else {
#pragma unroll
        for (int fm = 0; fm < 4; fm++) {
#pragma unroll
            for (int h = 0; h < 2; h++) {
                const int row = m0 + wm * 64 + fm * 16 + h * 8 + g;
                if (row < mlen) {
                    const int orig = g_perm[seg0 + row];
                    const float gg = gate[orig];
                    const int   dest = new_index[orig] >> 1;
                    float* orow = outp + (size_t)dest * HD + n0 + wn * 32 + q * 2;
#pragma unroll
                    for (int fn = 0; fn < 4; fn++) {
                        atomicAdd(orow + fn * 8 + 0, acc[fm][fn][h * 2 + 0] * gg);
                        atomicAdd(orow + fn * 8 + 1, acc[fm][fn][h * 2 + 1] * gg);
                    }
                }
            }
        }
    }
}

// ---------------- host: tensormap construction ----------------
typedef CUresult (*PFN_encodeTiled)(
    CUtensorMap*, CUtensorMapDataType, cuuint32_t, void*,
    const cuuint64_t*, const cuuint64_t*, const cuuint32_t*, const cuuint32_t*,
    CUtensorMapInterleave, CUtensorMapSwizzle, CUtensorMapL2promotion,
    CUtensorMapFloatOOBfill);

static void build_map(PFN_encodeTiled enc, CUtensorMap* out, void* base,
                      uint64_t d0, uint64_t d1, uint32_t b0, uint32_t b1) {
    cuuint64_t dims[2]    = { d0, d1 };
    cuuint64_t strides[1] = { d0 * 2 };   // bytes per row (fp16)
    cuuint32_t box[2]     = { b0, b1 };
    cuuint32_t es[2]      = { 1, 1 };
    enc(out, CU_TENSOR_MAP_DATA_TYPE_FLOAT16, 2, base, dims, strides, box, es,
        CU_TENSOR_MAP_INTERLEAVE_NONE, CU_TENSOR_MAP_SWIZZLE_128B,
        CU_TENSOR_MAP_L2_PROMOTION_L2_128B, CU_TENSOR_MAP_FLOAT_OOB_FILL_NONE);
}

// ---------------- launch ----------------
extern "C" void kernel_launch(void* const* d_in, const int* in_sizes, int n_in,
                              void* d_out, int out_size) {
    const float* x         = (const float*)d_in[0];
    const float* gate      = (const float*)d_in[1];
    const int*   experts   = (const int*)  d_in[2];
    const int*   new_index = (const int*)  d_in[3];
    const float* w1        = (const float*)d_in[4];
    const float* w2        = (const float*)d_in[5];
    float*       out       = (float*)d_out;

    cudaFuncSetAttribute(k_gemm<HD, true>,  cudaFuncAttributeMaxDynamicSharedMemorySize, SMEM_BYTES);
    cudaFuncSetAttribute(k_gemm<FD, false>, cudaFuncAttributeMaxDynamicSharedMemorySize, SMEM_BYTES);

    __half* w1h; __half* w2h; __half* xh; __half* hbuf;
    unsigned char* tmaps_d;
    cudaGetSymbolAddress((void**)&w1h,    g_w1h);
    cudaGetSymbolAddress((void**)&w2h,    g_w2h);
    cudaGetSymbolAddress((void**)&xh,     g_xh);
    cudaGetSymbolAddress((void**)&hbuf,   g_hbuf);
    cudaGetSymbolAddress((void**)&tmaps_d, g_tmaps);

    // build tensormaps (host-side, deterministic every call)
    static __align__(128) unsigned char h_tmaps[4 * 128];
    PFN_encodeTiled enc = nullptr;
    cudaDriverEntryPointQueryResult qr;
    cudaGetDriverEntryPoint("cuTensorMapEncodeTiled", (void**)&enc,
                            cudaEnableDefault, &qr);
    build_map(enc, (CUtensorMap*)(h_tmaps + 0),   w1h,  HD, (uint64_t)NE * FD, BK, BN);
    build_map(enc, (CUtensorMap*)(h_tmaps + 128), w2h,  FD, (uint64_t)NE * HD, BK, BN);
    build_map(enc, (CUtensorMap*)(h_tmaps + 256), hbuf, FD, (uint64_t)NT,      BK, BM);
    build_map(enc, (CUtensorMap*)(h_tmaps + 384), xh,   HD, (uint64_t)NT,      BK, BM);
    cudaMemcpyAsync(tmaps_d, h_tmaps, sizeof(h_tmaps), cudaMemcpyHostToDevice, 0);

    cudaMemsetAsync(d_out, 0, (size_t)out_size * sizeof(float), 0);

    // routing first (g_perm needed by the x gather in k_prep)
    k_route<<<1, 1024>>>(experts);
    // prep: blocks 0..4095 w1 cvt; 4096..5119 x gather+cvt (sorted order)
    k_prep<<<PREP_W1_BLKS + PREP_X_BLKS, 256>>>(
        (const float4*)w1, (const float4*)x);

    // fc1: gelu(xs @ w1^T) -> g_hbuf; + 16 trailing y-blocks convert w2 -> g_w2h
    k_gemm<HD, true><<<dim3(FD / BN, MAXT + 16), 512, SMEM_BYTES>>>(
        tmaps_d + 384, tmaps_d + 0, gate, new_index, out, w2);
    // fc2: (hbuf @ w2^T) * gate -> atomicAdd topk-scatter
    k_gemm<FD, false><<<dim3(HD / BN, MAXT), 512, SMEM_BYTES>>>(
        tmaps_d + 256, tmaps_d + 128, gate, new_index, out, nullptr);
}